// round 5
// baseline (speedup 1.0000x reference)
#include <cuda_runtime.h>
#include <cuda_bf16.h>
#include <cstddef>

// Problem constants
#define NB   16
#define NH   64
#define NW   64
#define NC   512
#define NIC  64
#define NROWS (NB*NH*NW)          // 65536
#define LN_EPS 1e-3f

// Scratch: g, h, p  (each NROWS x NIC floats = 16 MB)
__device__ float d_G[(size_t)NROWS * NIC];
__device__ float d_H[(size_t)NROWS * NIC];
__device__ float d_P[(size_t)NROWS * NIC];

// ---------------------------------------------------------------------------
// K1: G = LN_f(x @ w_f), H = LN_h(x @ w_h)
// GEMM M=65536, N=128 (w_f cols 0..63 | w_h cols 64..127), K=512.
// Block tile 128x128, BK=16, 256 threads, 8x8 register tile per thread.
// LN over each 64-wide half via 8-lane shfl reduction in the epilogue.
// ---------------------------------------------------------------------------
#define K1_BM 128
#define K1_BN 128
#define K1_BK 16

__global__ __launch_bounds__(256)
void k1_gemm_ln(const float* __restrict__ x,
                const float* __restrict__ wf, const float* __restrict__ wh,
                const float* __restrict__ gamma_f, const float* __restrict__ beta_f,
                const float* __restrict__ gamma_h, const float* __restrict__ beta_h)
{
    __shared__ float As[K1_BK][K1_BM];   // x^T tile: As[kk][m]
    __shared__ float Bs[K1_BK][K1_BN];   // [wf | wh]

    const int tid  = threadIdx.x;
    const int row0 = blockIdx.x * K1_BM;
    const int tm   = (tid >> 4) << 3;    // 0..120
    const int tn   = (tid & 15) << 3;    // 0..120

    float acc[8][8];
#pragma unroll
    for (int i = 0; i < 8; i++)
#pragma unroll
        for (int j = 0; j < 8; j++) acc[i][j] = 0.0f;

    const int am  = tid >> 1;            // row within A tile (0..127)
    const int ac0 = (tid & 1) * 2;       // float4 chunk base along k

    for (int k0 = 0; k0 < NC; k0 += K1_BK) {
        // ---- load A (x), transposed into smem ----
#pragma unroll
        for (int s = 0; s < 2; s++) {
            const int chunk = ac0 + s;   // 0..3
            const float4 v = *reinterpret_cast<const float4*>(
                x + (size_t)(row0 + am) * NC + k0 + chunk * 4);
            As[chunk * 4 + 0][am] = v.x;
            As[chunk * 4 + 1][am] = v.y;
            As[chunk * 4 + 2][am] = v.z;
            As[chunk * 4 + 3][am] = v.w;
        }
        // ---- load B = [wf | wh] tile 16 x 128 ----
#pragma unroll
        for (int it = 0; it < 2; it++) {
            const int f    = tid + it * 256;     // 0..511 float4 index
            const int kk   = f >> 5;             // 0..15
            const int col4 = (f & 31) * 4;       // 0..124
            const float* src = (col4 < NIC)
                ? (wf + (size_t)(k0 + kk) * NIC + col4)
                : (wh + (size_t)(k0 + kk) * NIC + (col4 - NIC));
            *reinterpret_cast<float4*>(&Bs[kk][col4]) =
                *reinterpret_cast<const float4*>(src);
        }
        __syncthreads();

#pragma unroll
        for (int kk = 0; kk < K1_BK; kk++) {
            float a[8], b[8];
            *reinterpret_cast<float4*>(&a[0]) = *reinterpret_cast<const float4*>(&As[kk][tm]);
            *reinterpret_cast<float4*>(&a[4]) = *reinterpret_cast<const float4*>(&As[kk][tm + 4]);
            *reinterpret_cast<float4*>(&b[0]) = *reinterpret_cast<const float4*>(&Bs[kk][tn]);
            *reinterpret_cast<float4*>(&b[4]) = *reinterpret_cast<const float4*>(&Bs[kk][tn + 4]);
#pragma unroll
            for (int i = 0; i < 8; i++)
#pragma unroll
                for (int j = 0; j < 8; j++)
                    acc[i][j] = fmaf(a[i], b[j], acc[i][j]);
        }
        __syncthreads();
    }

    // ---- LayerNorm epilogue (per row, per 64-wide half) ----
    // Each (row-group, half) is owned by an aligned set of 8 consecutive lanes.
    const bool isF   = (tn < NIC);
    const int  cbase = tn & (NIC - 1);
    const float* gam = isF ? gamma_f : gamma_h;
    const float* bet = isF ? beta_f  : beta_h;
    float gmv[8], btv[8];
#pragma unroll
    for (int j = 0; j < 8; j++) { gmv[j] = gam[cbase + j]; btv[j] = bet[cbase + j]; }
    float* dstBase = isF ? d_G : d_H;

#pragma unroll
    for (int rr = 0; rr < 8; rr++) {
        float s = 0.0f, ss = 0.0f;
#pragma unroll
        for (int j = 0; j < 8; j++) { const float v = acc[rr][j]; s += v; ss += v * v; }
#pragma unroll
        for (int o = 1; o < 8; o <<= 1) {
            s  += __shfl_xor_sync(0xffffffffu, s,  o);
            ss += __shfl_xor_sync(0xffffffffu, ss, o);
        }
        const float mean = s * (1.0f / NIC);
        const float var  = ss * (1.0f / NIC) - mean * mean;
        const float inv  = rsqrtf(var + LN_EPS);
        float ov[8];
#pragma unroll
        for (int j = 0; j < 8; j++)
            ov[j] = (acc[rr][j] - mean) * inv * gmv[j] + btv[j];
        float* dst = dstBase + (size_t)(row0 + tm + rr) * NIC + cbase;
        *reinterpret_cast<float4*>(dst)     = *reinterpret_cast<float4*>(&ov[0]);
        *reinterpret_cast<float4*>(dst + 4) = *reinterpret_cast<float4*>(&ov[4]);
    }
}

// ---------------------------------------------------------------------------
// K2: P[b,h,w,i] = softmax_h( G[b,w,h,i] * G[b,h,w,i] ) * H[b,h,w,i]
// One block per (b,w). thread = (i = tid%64, h-quarter q = tid/64).
// All global accesses coalesced along i.
// ---------------------------------------------------------------------------
__global__ __launch_bounds__(256)
void k2_softmax()
{
    __shared__ float red[4][64];
    const int tid = threadIdx.x;
    const int b   = blockIdx.x >> 6;
    const int w   = blockIdx.x & 63;
    const int i   = tid & 63;
    const int q   = tid >> 6;
    const int h0  = q * 16;

    float l[16];
#pragma unroll
    for (int hh = 0; hh < 16; hh++) {
        const int h = h0 + hh;
        const float gw = d_G[((size_t)((b * NH + w) * NW + h)) * NIC + i]; // g[b,w,h,i]
        const float gc = d_G[((size_t)((b * NH + h) * NW + w)) * NIC + i]; // g[b,h,w,i]
        l[hh] = gw * gc;
    }
    float m = l[0];
#pragma unroll
    for (int hh = 1; hh < 16; hh++) m = fmaxf(m, l[hh]);
    red[q][i] = m;
    __syncthreads();
    const float M = fmaxf(fmaxf(red[0][i], red[1][i]), fmaxf(red[2][i], red[3][i]));
    __syncthreads();

    float s = 0.0f;
#pragma unroll
    for (int hh = 0; hh < 16; hh++) {
        const float e = __expf(l[hh] - M);
        l[hh] = e;
        s += e;
    }
    red[q][i] = s;
    __syncthreads();
    const float S    = red[0][i] + red[1][i] + red[2][i] + red[3][i];
    const float rinv = 1.0f / S;

#pragma unroll
    for (int hh = 0; hh < 16; hh++) {
        const int h = h0 + hh;
        const size_t o = ((size_t)((b * NH + h) * NW + w)) * NIC + i;
        d_P[o] = l[hh] * rinv * d_H[o];
    }
}

// ---------------------------------------------------------------------------
// K3: out = x + LN_fgh(P @ w_fgh) * scale
// GEMM M=65536, N=512 (full C per block -> LN fusable), K=64.
// Block tile 32x512, BK=16, 256 threads, 8x8 register tile.
// Row LN: full-warp shfl reduce + 2-warp smem combine.
// ---------------------------------------------------------------------------
#define K3_BM 32
#define K3_BK 16

__global__ __launch_bounds__(256)
void k3_gemm_ln_res(const float* __restrict__ wfgh,
                    const float* __restrict__ gamma, const float* __restrict__ beta,
                    const float* __restrict__ scale,
                    const float* __restrict__ x,
                    float* __restrict__ out)
{
    __shared__ float As[K3_BK][K3_BM];       // P^T tile
    __shared__ float Bs[K3_BK][NC];          // 32 KB
    __shared__ float red2[4][8][2][2];       // [group][rr][warp-parity][{sum,sumsq}]

    const int tid  = threadIdx.x;
    const int row0 = blockIdx.x * K3_BM;
    const int g    = tid >> 6;               // row group 0..3
    const int tm   = g << 3;                 // 0,8,16,24
    const int tn   = (tid & 63) << 3;        // 0..504
    const int wp   = (tid >> 5) & 1;         // warp parity within group
    const int lane = tid & 31;

    float acc[8][8];
#pragma unroll
    for (int i = 0; i < 8; i++)
#pragma unroll
        for (int j = 0; j < 8; j++) acc[i][j] = 0.0f;

    for (int k0 = 0; k0 < NIC; k0 += K3_BK) {
        if (tid < 128) {                     // A: 32x16 = 128 float4
            const int m     = tid >> 2;
            const int chunk = tid & 3;
            const float4 v = *reinterpret_cast<const float4*>(
                d_P + (size_t)(row0 + m) * NIC + k0 + chunk * 4);
            As[chunk * 4 + 0][m] = v.x;
            As[chunk * 4 + 1][m] = v.y;
            As[chunk * 4 + 2][m] = v.z;
            As[chunk * 4 + 3][m] = v.w;
        }
#pragma unroll
        for (int it = 0; it < 8; it++) {     // B: 16x512 = 2048 float4
            const int f  = tid + it * 256;
            const int kk = f >> 7;           // 0..15
            const int c4 = (f & 127) * 4;    // 0..508
            *reinterpret_cast<float4*>(&Bs[kk][c4]) =
                *reinterpret_cast<const float4*>(wfgh + (size_t)(k0 + kk) * NC + c4);
        }
        __syncthreads();

#pragma unroll
        for (int kk = 0; kk < K3_BK; kk++) {
            float a[8], b[8];
            *reinterpret_cast<float4*>(&a[0]) = *reinterpret_cast<const float4*>(&As[kk][tm]);
            *reinterpret_cast<float4*>(&a[4]) = *reinterpret_cast<const float4*>(&As[kk][tm + 4]);
            *reinterpret_cast<float4*>(&b[0]) = *reinterpret_cast<const float4*>(&Bs[kk][tn]);
            *reinterpret_cast<float4*>(&b[4]) = *reinterpret_cast<const float4*>(&Bs[kk][tn + 4]);
#pragma unroll
            for (int i = 0; i < 8; i++)
#pragma unroll
                for (int j = 0; j < 8; j++)
                    acc[i][j] = fmaf(a[i], b[j], acc[i][j]);
        }
        __syncthreads();
    }

    // ---- per-row LN reduction: warp shfl then 2-warp combine ----
#pragma unroll
    for (int rr = 0; rr < 8; rr++) {
        float s = 0.0f, ss = 0.0f;
#pragma unroll
        for (int j = 0; j < 8; j++) { const float v = acc[rr][j]; s += v; ss += v * v; }
#pragma unroll
        for (int o = 1; o < 32; o <<= 1) {
            s  += __shfl_xor_sync(0xffffffffu, s,  o);
            ss += __shfl_xor_sync(0xffffffffu, ss, o);
        }
        if (lane == 0) { red2[g][rr][wp][0] = s; red2[g][rr][wp][1] = ss; }
    }
    __syncthreads();

    const float sc = scale[0];
    float gmv[8], btv[8];
#pragma unroll
    for (int j = 0; j < 8; j++) { gmv[j] = gamma[tn + j]; btv[j] = beta[tn + j]; }

#pragma unroll
    for (int rr = 0; rr < 8; rr++) {
        const float S    = red2[g][rr][0][0] + red2[g][rr][1][0];
        const float SS   = red2[g][rr][0][1] + red2[g][rr][1][1];
        const float mean = S * (1.0f / NC);
        const float var  = SS * (1.0f / NC) - mean * mean;
        const float inv  = rsqrtf(var + LN_EPS);
        const size_t r   = (size_t)(row0 + tm + rr);

        float xv[8];
        *reinterpret_cast<float4*>(&xv[0]) = *reinterpret_cast<const float4*>(x + r * NC + tn);
        *reinterpret_cast<float4*>(&xv[4]) = *reinterpret_cast<const float4*>(x + r * NC + tn + 4);

        float ov[8];
#pragma unroll
        for (int j = 0; j < 8; j++)
            ov[j] = xv[j] + ((acc[rr][j] - mean) * inv * gmv[j] + btv[j]) * sc;

        float* dst = out + r * NC + tn;
        *reinterpret_cast<float4*>(dst)     = *reinterpret_cast<float4*>(&ov[0]);
        *reinterpret_cast<float4*>(dst + 4) = *reinterpret_cast<float4*>(&ov[4]);
    }
}

// ---------------------------------------------------------------------------
// Launch. Inputs (metadata order):
// 0:x 1:w_f 2:w_h 3:w_fgh 4:gamma_f 5:beta_f 6:gamma_h 7:beta_h
// 8:gamma_fgh 9:beta_fgh 10:scale
// ---------------------------------------------------------------------------
extern "C" void kernel_launch(void* const* d_in, const int* in_sizes, int n_in,
                              void* d_out, int out_size)
{
    (void)in_sizes; (void)n_in; (void)out_size;
    const float* x         = (const float*)d_in[0];
    const float* w_f       = (const float*)d_in[1];
    const float* w_h       = (const float*)d_in[2];
    const float* w_fgh     = (const float*)d_in[3];
    const float* gamma_f   = (const float*)d_in[4];
    const float* beta_f    = (const float*)d_in[5];
    const float* gamma_h   = (const float*)d_in[6];
    const float* beta_h    = (const float*)d_in[7];
    const float* gamma_fgh = (const float*)d_in[8];
    const float* beta_fgh  = (const float*)d_in[9];
    const float* scale     = (const float*)d_in[10];
    float* out             = (float*)d_out;

    k1_gemm_ln<<<NROWS / K1_BM, 256>>>(x, w_f, w_h,
                                       gamma_f, beta_f, gamma_h, beta_h);
    k2_softmax<<<NB * NW, 256>>>();
    k3_gemm_ln_res<<<NROWS / K3_BM, 256>>>(w_fgh, gamma_fgh, beta_fgh,
                                           scale, x, out);
}